// round 4
// baseline (speedup 1.0000x reference)
#include <cuda_runtime.h>
#include <math.h>

// Problem constants (fixed by setup_inputs)
#define S     2048   // sequence / block size
#define HID   2048   // hidden dim
#define NHEAD 16
#define HDIM  128
#define HDTOT 2048   // NHEAD * HDIM
#define RING_REST 3.0f   // world_size - 1 (non-causal ring steps, all identical)

// ---------------- static device scratch (no allocations allowed) ----------------
__device__ float g_q   [S * HDTOT];               // (S, H*D) fp32, 16 MB
__device__ float g_k   [S * HDTOT];               // (S, H*D)
__device__ float g_vt  [HDTOT * S];               // (H*D, S)  = V transposed per head
__device__ float g_attn[S * HDTOT];               // (S, H*D) attention output
__device__ float g_scores[NHEAD * S * S];         // (H, S, S) scores -> weights, 256 MB

// ---------------- generic fp32 SGEMM:  C = alpha * A(M,K) * B(N,K)^T + bias ----------------
// mode 0: C[m*ldc + n]        mode 2: C[n*ldc + m]
#define BM 128
#define BN 128
#define BK 8

__global__ __launch_bounds__(256, 2)
void sgemm_nt(const float* __restrict__ A, int lda, long long sAz,
              const float* __restrict__ B, int ldb, long long sBz,
              const float* __restrict__ bias,
              float* __restrict__ C, int ldc, long long sCz,
              int K, float alpha, int mode)
{
    A += (long long)blockIdx.z * sAz;
    B += (long long)blockIdx.z * sBz;
    C += (long long)blockIdx.z * sCz;

    __shared__ float As[BK][BM + 4];
    __shared__ float Bs[BK][BN + 4];

    const int tid = threadIdx.x;
    const int m0 = blockIdx.y * BM;
    const int n0 = blockIdx.x * BN;

    // loader mapping: 256 threads, each thread one float4 of A-tile and one of B-tile
    const int aRow = tid >> 1;          // 0..127
    const int aK   = (tid & 1) * 4;     // 0 or 4

    const float* Aptr = A + (size_t)(m0 + aRow) * lda + aK;
    const float* Bptr = B + (size_t)(n0 + aRow) * ldb + aK;

    const int ty = tid >> 4;   // 0..15
    const int tx = tid & 15;   // 0..15

    float acc[8][8];
#pragma unroll
    for (int i = 0; i < 8; ++i)
#pragma unroll
        for (int j = 0; j < 8; ++j) acc[i][j] = 0.f;

    for (int k0 = 0; k0 < K; k0 += BK) {
        float4 av = *(const float4*)(Aptr + k0);
        float4 bv = *(const float4*)(Bptr + k0);
        __syncthreads();
        As[aK + 0][aRow] = av.x; As[aK + 1][aRow] = av.y;
        As[aK + 2][aRow] = av.z; As[aK + 3][aRow] = av.w;
        Bs[aK + 0][aRow] = bv.x; Bs[aK + 1][aRow] = bv.y;
        Bs[aK + 2][aRow] = bv.z; Bs[aK + 3][aRow] = bv.w;
        __syncthreads();
#pragma unroll
        for (int k = 0; k < BK; ++k) {
            float ra[8], rb[8];
#pragma unroll
            for (int i = 0; i < 8; ++i) ra[i] = As[k][ty * 8 + i];
#pragma unroll
            for (int j = 0; j < 8; ++j) rb[j] = Bs[k][tx * 8 + j];
#pragma unroll
            for (int i = 0; i < 8; ++i)
#pragma unroll
                for (int j = 0; j < 8; ++j)
                    acc[i][j] = fmaf(ra[i], rb[j], acc[i][j]);
        }
    }

    float bvreg[8];
#pragma unroll
    for (int j = 0; j < 8; ++j)
        bvreg[j] = bias ? bias[n0 + tx * 8 + j] : 0.f;

    if (mode == 0) {
#pragma unroll
        for (int i = 0; i < 8; ++i) {
            float* crow = C + (size_t)(m0 + ty * 8 + i) * ldc + n0 + tx * 8;
            float4 w0, w1;
            w0.x = acc[i][0] * alpha + bvreg[0];
            w0.y = acc[i][1] * alpha + bvreg[1];
            w0.z = acc[i][2] * alpha + bvreg[2];
            w0.w = acc[i][3] * alpha + bvreg[3];
            w1.x = acc[i][4] * alpha + bvreg[4];
            w1.y = acc[i][5] * alpha + bvreg[5];
            w1.z = acc[i][6] * alpha + bvreg[6];
            w1.w = acc[i][7] * alpha + bvreg[7];
            *(float4*)(crow)     = w0;
            *(float4*)(crow + 4) = w1;
        }
    } else {
        // transposed store: C[n*ldc + m]; m values are consecutive -> float4
#pragma unroll
        for (int j = 0; j < 8; ++j) {
            float* ccol = C + (size_t)(n0 + tx * 8 + j) * ldc + m0 + ty * 8;
            float4 w0, w1;
            w0.x = acc[0][j] * alpha + bvreg[j];
            w0.y = acc[1][j] * alpha + bvreg[j];
            w0.z = acc[2][j] * alpha + bvreg[j];
            w0.w = acc[3][j] * alpha + bvreg[j];
            w1.x = acc[4][j] * alpha + bvreg[j];
            w1.y = acc[5][j] * alpha + bvreg[j];
            w1.z = acc[6][j] * alpha + bvreg[j];
            w1.w = acc[7][j] * alpha + bvreg[j];
            *(float4*)(ccol)     = w0;
            *(float4*)(ccol + 4) = w1;
        }
    }
}

// ---------------- ring-softmax weight transform ----------------
// In-place on g_scores: scores -> combined attention weights.
// w_j = [ 3*e^{s_j-mB}/(lB+1e-8) + (j<=row) * e^{mC-mB} * e^{s_j-mC}/(lC+1e-8) ]
//       / ( e^{mC-mB}*lC + 3*lB + 1e-8 )
__global__ __launch_bounds__(256)
void ring_softmax(float* __restrict__ scores)
{
    const int row = blockIdx.x;
    float* p = scores + ((size_t)blockIdx.y * S + row) * S;
    const int tid = threadIdx.x;

    float v[8];
    float mB = -3.0e38f, mC = -3.0e38f;
#pragma unroll
    for (int t = 0; t < 8; ++t) {
        int j = t * 256 + tid;
        v[t] = p[j];
        mB = fmaxf(mB, v[t]);
        if (j <= row) mC = fmaxf(mC, v[t]);
    }

    __shared__ float sm0[8], sm1[8];
    const int wid = tid >> 5, lid = tid & 31;
#pragma unroll
    for (int o = 16; o > 0; o >>= 1) {
        mB = fmaxf(mB, __shfl_xor_sync(0xffffffffu, mB, o));
        mC = fmaxf(mC, __shfl_xor_sync(0xffffffffu, mC, o));
    }
    if (lid == 0) { sm0[wid] = mB; sm1[wid] = mC; }
    __syncthreads();
    mB = sm0[0]; mC = sm1[0];
#pragma unroll
    for (int i = 1; i < 8; ++i) { mB = fmaxf(mB, sm0[i]); mC = fmaxf(mC, sm1[i]); }
    __syncthreads();   // done reading sm0/sm1 before reuse

    float eb[8];
    float sB = 0.f, sC = 0.f;
#pragma unroll
    for (int t = 0; t < 8; ++t) {
        int j = t * 256 + tid;
        eb[t] = expf(v[t] - mB);
        sB += eb[t];
        if (j <= row) sC += expf(v[t] - mC);
    }
#pragma unroll
    for (int o = 16; o > 0; o >>= 1) {
        sB += __shfl_xor_sync(0xffffffffu, sB, o);
        sC += __shfl_xor_sync(0xffffffffu, sC, o);
    }
    if (lid == 0) { sm0[wid] = sB; sm1[wid] = sC; }
    __syncthreads();
    sB = 0.f; sC = 0.f;
#pragma unroll
    for (int i = 0; i < 8; ++i) { sB += sm0[i]; sC += sm1[i]; }

    const float e     = expf(mC - mB);                      // <= 1, never underflows here
    const float cb    = RING_REST / (sB + 1e-8f);
    const float cc    = e / (sC + 1e-8f);
    const float invSe = 1.0f / (e * sC + RING_REST * sB + 1e-8f);
#pragma unroll
    for (int t = 0; t < 8; ++t) {
        int j = t * 256 + tid;
        float w = eb[t] * cb;
        if (j <= row) w += expf(v[t] - mC) * cc;
        p[j] = w * invSe;
    }
}

// ---------------- launch ----------------
extern "C" void kernel_launch(void* const* d_in, const int* in_sizes, int n_in,
                              void* d_out, int out_size)
{
    (void)in_sizes; (void)n_in; (void)out_size;
    const float* X  = (const float*)d_in[0];
    const float* qw = (const float*)d_in[1];
    const float* qb = (const float*)d_in[2];
    const float* kw = (const float*)d_in[3];
    const float* kb = (const float*)d_in[4];
    const float* vw = (const float*)d_in[5];
    const float* vb = (const float*)d_in[6];
    const float* ow = (const float*)d_in[7];
    const float* ob = (const float*)d_in[8];
    float* out = (float*)d_out;

    float *gq, *gk, *gvt, *gattn, *gs;
    cudaGetSymbolAddress((void**)&gq,    g_q);
    cudaGetSymbolAddress((void**)&gk,    g_k);
    cudaGetSymbolAddress((void**)&gvt,   g_vt);
    cudaGetSymbolAddress((void**)&gattn, g_attn);
    cudaGetSymbolAddress((void**)&gs,    g_scores);

    const float scale = 0.08838834764831843f;   // 1/sqrt(128)
    dim3 blk(256);

    // Q = X @ qw^T + qb            (S, H*D)
    sgemm_nt<<<dim3(HDTOT/BN, S/BM, 1), blk>>>(X, HID, 0, qw, HID, 0, qb,
                                               gq, HDTOT, 0, HID, 1.0f, 0);
    // K = X @ kw^T + kb            (S, H*D)
    sgemm_nt<<<dim3(HDTOT/BN, S/BM, 1), blk>>>(X, HID, 0, kw, HID, 0, kb,
                                               gk, HDTOT, 0, HID, 1.0f, 0);
    // V^T = (X @ vw^T + vb)^T      (H*D, S)
    sgemm_nt<<<dim3(HDTOT/BN, S/BM, 1), blk>>>(X, HID, 0, vw, HID, 0, vb,
                                               gvt, S, 0, HID, 1.0f, 2);

    // scores[h] = scale * Q_h @ K_h^T   (per head, K = 128)
    sgemm_nt<<<dim3(S/BN, S/BM, NHEAD), blk>>>(gq, HDTOT, (long long)HDIM,
                                               gk, HDTOT, (long long)HDIM,
                                               nullptr,
                                               gs, S, (long long)S * S,
                                               HDIM, scale, 0);

    // scores -> combined ring-softmax weights (in place)
    ring_softmax<<<dim3(S, NHEAD), blk>>>(gs);

    // attn[h] = W_h @ V_h          (S, 128) written into (S, H*D) at col h*128
    sgemm_nt<<<dim3(HDIM/BN + (HDIM%BN ? 1 : 0), S/BM, NHEAD), blk>>>(
        gs, S, (long long)S * S,
        gvt, S, (long long)HDIM * S,
        nullptr,
        gattn, HDTOT, (long long)HDIM,
        S, 1.0f, 0);

    // out = attn @ ow^T + ob       (S, HID)
    sgemm_nt<<<dim3(HID/BN, S/BM, 1), blk>>>(gattn, HDTOT, 0, ow, HID, 0, ob,
                                             out, HID, 0, HDTOT, 1.0f, 0);
}

// round 7
// speedup vs baseline: 2.1719x; 2.1719x over previous
#include <cuda_runtime.h>
#include <cuda_bf16.h>
#include <stdint.h>
#include <math.h>

// Problem constants (fixed by setup_inputs)
#define S     2048
#define HID   2048
#define NHEAD 16
#define HDIM  128
#define HDTOT 2048
#define RING_REST 3.0f   // world_size - 1 identical non-causal ring steps

typedef __nv_bfloat16 bf16;

// ---------------- static device scratch (no runtime allocation allowed) ----------------
__device__ bf16  g_Xh [S * HID],     g_Xl [S * HID];
__device__ bf16  g_qwh[HDTOT * HID], g_qwl[HDTOT * HID];
__device__ bf16  g_kwh[HDTOT * HID], g_kwl[HDTOT * HID];
__device__ bf16  g_vwh[HDTOT * HID], g_vwl[HDTOT * HID];
__device__ bf16  g_owh[HID * HDTOT], g_owl[HID * HDTOT];
__device__ float g_q   [S * HDTOT];
__device__ float g_k   [S * HDTOT];
__device__ float g_v   [S * HDTOT];
__device__ float g_attn[S * HDTOT];
__device__ bf16  g_qh [S * HDTOT], g_ql [S * HDTOT];
__device__ bf16  g_kh [S * HDTOT], g_kl [S * HDTOT];
__device__ bf16  g_vth[HDTOT * S], g_vtl[HDTOT * S];   // V transposed (H*D, S)
__device__ bf16  g_ath[S * HDTOT], g_atl[S * HDTOT];
__device__ float g_scores[(size_t)NHEAD * S * S];      // 256 MB
__device__ bf16  g_wh[(size_t)NHEAD * S * S];          // attention weights hi
__device__ bf16  g_wl[(size_t)NHEAD * S * S];          // attention weights lo

// ---------------- PTX helpers (base compute_103 features only) ----------------
__device__ __forceinline__ uint32_t smem_u32(const void* p) {
    uint32_t a;
    asm("{ .reg .u64 t; cvta.to.shared.u64 t, %1; cvt.u32.u64 %0, t; }" : "=r"(a) : "l"(p));
    return a;
}
__device__ __forceinline__ void cp16(uint32_t s, const void* g) {
    asm volatile("cp.async.cg.shared.global [%0], [%1], 16;" :: "r"(s), "l"(g));
}
#define CP_COMMIT() asm volatile("cp.async.commit_group;" ::: "memory")

#define LDSM4(r, addr) \
    asm volatile("ldmatrix.sync.aligned.m8n8.x4.shared.b16 {%0,%1,%2,%3}, [%4];" \
        : "=r"((r)[0]), "=r"((r)[1]), "=r"((r)[2]), "=r"((r)[3]) : "r"(addr))

#define MMA(cc, aa, b0, b1) \
    asm volatile("mma.sync.aligned.m16n8k16.row.col.f32.bf16.bf16.f32 " \
        "{%0,%1,%2,%3}, {%4,%5,%6,%7}, {%8,%9}, {%0,%1,%2,%3};" \
        : "+f"((cc)[0]), "+f"((cc)[1]), "+f"((cc)[2]), "+f"((cc)[3]) \
        : "r"((aa)[0]), "r"((aa)[1]), "r"((aa)[2]), "r"((aa)[3]), "r"(b0), "r"(b1))

// ---------------- split / transpose conversion kernels ----------------
__global__ __launch_bounds__(256)
void split_k(const float* __restrict__ s, bf16* __restrict__ h, bf16* __restrict__ l, int n4) {
    int i = blockIdx.x * blockDim.x + threadIdx.x;
    if (i >= n4) return;
    float4 v = ((const float4*)s)[i];
    bf16 h0 = __float2bfloat16_rn(v.x), h1 = __float2bfloat16_rn(v.y);
    bf16 h2 = __float2bfloat16_rn(v.z), h3 = __float2bfloat16_rn(v.w);
    bf16 l0 = __float2bfloat16_rn(v.x - __bfloat162float(h0));
    bf16 l1 = __float2bfloat16_rn(v.y - __bfloat162float(h1));
    bf16 l2 = __float2bfloat16_rn(v.z - __bfloat162float(h2));
    bf16 l3 = __float2bfloat16_rn(v.w - __bfloat162float(h3));
    ((__nv_bfloat162*)h)[2 * i]     = __halves2bfloat162(h0, h1);
    ((__nv_bfloat162*)h)[2 * i + 1] = __halves2bfloat162(h2, h3);
    ((__nv_bfloat162*)l)[2 * i]     = __halves2bfloat162(l0, l1);
    ((__nv_bfloat162*)l)[2 * i + 1] = __halves2bfloat162(l2, l3);
}

__global__ __launch_bounds__(256)
void transpose_split_k(const float* __restrict__ src, bf16* __restrict__ th, bf16* __restrict__ tl) {
    __shared__ float tile[32][33];
    int c0 = blockIdx.x * 32, r0 = blockIdx.y * 32;
    int x = threadIdx.x, y = threadIdx.y;   // block (32,8)
#pragma unroll
    for (int i = 0; i < 32; i += 8)
        tile[y + i][x] = src[(size_t)(r0 + y + i) * HDTOT + (c0 + x)];
    __syncthreads();
#pragma unroll
    for (int i = 0; i < 32; i += 8) {
        float v = tile[x][y + i];              // src[r0+x][c0+y+i]
        bf16 h = __float2bfloat16_rn(v);
        size_t o = (size_t)(c0 + y + i) * S + (r0 + x);
        th[o] = h;
        tl[o] = __float2bfloat16_rn(v - __bfloat162float(h));
    }
}

// ---------------- split-bf16 GEMM via mma.sync:  C = alpha*(A*B^T) + bias ----------------
// A (M,K) via Ah/Al, B (N,K) via Bh/Bl, row-major bf16. CTA tile 128x128, BK=32.
// 8 warps as 2(m) x 4(n); warp tile 64x32. 2-stage cp.async pipeline.
// smem per stage: Ah|Al|Bh|Bl each 128x32 bf16 = 8KB -> 32KB; 2 stages = 64KB.
#define GEMM_SMEM_BYTES 65536

__global__ __launch_bounds__(256)
void gemm_bf3(const bf16* __restrict__ Ah, const bf16* __restrict__ Al, int lda, long long sAz,
              const bf16* __restrict__ Bh, const bf16* __restrict__ Bl, int ldb, long long sBz,
              const float* __restrict__ bias,
              float* __restrict__ C, int ldc, long long sCz,
              int K, float alpha)
{
    extern __shared__ char smdyn[];
    __shared__ float bS[128];
    const uint32_t smb = smem_u32(smdyn);
    const int tid = threadIdx.x, lane = tid & 31, wid = tid >> 5;
    const int m0 = blockIdx.y * 128, n0 = blockIdx.x * 128;
    const int wm = (wid >> 2) * 64, wn = (wid & 3) * 32;

    Ah += (size_t)blockIdx.z * sAz;  Al += (size_t)blockIdx.z * sAz;
    Bh += (size_t)blockIdx.z * sBz;  Bl += (size_t)blockIdx.z * sBz;
    C  += (size_t)blockIdx.z * sCz;

    if (tid < 128) bS[tid] = bias ? bias[n0 + tid] : 0.f;

    // ---- loader mapping: thread -> (row, chunk pair). 512 chunks (16B) per buffer.
    const int idr = tid >> 1;           // row 0..127
    const int idc = (tid & 1) * 2;      // chunk 0 or 2
    const uint32_t swl = (idr >> 1) & 3;
    const uint32_t s0 = idr * 64 + ((idc ^ swl) << 4);
    const uint32_t s1 = idr * 64 + (((idc + 1) ^ swl) << 4);
    const bf16* gAh = Ah + (size_t)(m0 + idr) * lda + idc * 8;
    const bf16* gAl = Al + (size_t)(m0 + idr) * lda + idc * 8;
    const bf16* gBh = Bh + (size_t)(n0 + idr) * ldb + idc * 8;
    const bf16* gBl = Bl + (size_t)(n0 + idr) * ldb + idc * 8;

#define ISSUE(stg, kt) do {                                                    \
        uint32_t _b = smb + (stg) * 32768;                                     \
        cp16(_b +         s0, gAh + (kt)); cp16(_b +         s1, gAh + (kt) + 8); \
        cp16(_b +  8192 + s0, gAl + (kt)); cp16(_b +  8192 + s1, gAl + (kt) + 8); \
        cp16(_b + 16384 + s0, gBh + (kt)); cp16(_b + 16384 + s1, gBh + (kt) + 8); \
        cp16(_b + 24576 + s0, gBl + (kt)); cp16(_b + 24576 + s1, gBl + (kt) + 8); \
        CP_COMMIT();                                                           \
    } while (0)

    float c[4][4][4];
#pragma unroll
    for (int i = 0; i < 4; ++i)
#pragma unroll
        for (int j = 0; j < 4; ++j)
#pragma unroll
            for (int r = 0; r < 4; ++r) c[i][j][r] = 0.f;

    // lane-fixed pieces of ldmatrix addressing
    const int arow_l = lane & 15;                 // A: row within 16-row tile
    const int achk_l = lane >> 4;                 // A: k-chunk select (0/1)
    const int brow_l = (lane & 7) + ((lane >> 4) << 3);  // B: row within 16-n pair
    const int bchk_l = (lane >> 3) & 1;           // B: k-chunk select (0/1)

    const int nk = K / 32;
    ISSUE(0, 0);

    for (int kt = 0; kt < nk; ++kt) {
        if (kt + 1 < nk) {
            ISSUE((kt + 1) & 1, (kt + 1) * 32);
            asm volatile("cp.async.wait_group 1;" ::: "memory");
        } else {
            asm volatile("cp.async.wait_group 0;" ::: "memory");
        }
        __syncthreads();

        const uint32_t base = smb + (kt & 1) * 32768;
#pragma unroll
        for (int kk = 0; kk < 2; ++kk) {          // two k16 halves of BK=32
            const int c0 = kk * 2;
            uint32_t a_h[4][4], a_l[4][4];
            const int ac = c0 + achk_l;
#pragma unroll
            for (int i = 0; i < 4; ++i) {
                int row = wm + i * 16 + arow_l;
                uint32_t ph = row * 64 + ((ac ^ ((row >> 1) & 3)) << 4);
                LDSM4(a_h[i], base + ph);
                LDSM4(a_l[i], base + 8192 + ph);
            }
            uint32_t b_h[4][2], b_l[4][2];
            const int bc = c0 + bchk_l;
#pragma unroll
            for (int j2 = 0; j2 < 2; ++j2) {
                int row = wn + j2 * 16 + brow_l;
                uint32_t ph = row * 64 + ((bc ^ ((row >> 1) & 3)) << 4);
                uint32_t r[4];
                LDSM4(r, base + 16384 + ph);
                b_h[2 * j2][0] = r[0]; b_h[2 * j2][1] = r[1];
                b_h[2 * j2 + 1][0] = r[2]; b_h[2 * j2 + 1][1] = r[3];
                LDSM4(r, base + 24576 + ph);
                b_l[2 * j2][0] = r[0]; b_l[2 * j2][1] = r[1];
                b_l[2 * j2 + 1][0] = r[2]; b_l[2 * j2 + 1][1] = r[3];
            }
#pragma unroll
            for (int i = 0; i < 4; ++i)
#pragma unroll
                for (int j = 0; j < 4; ++j) {
                    MMA(c[i][j], a_h[i], b_h[j][0], b_h[j][1]);
                    MMA(c[i][j], a_h[i], b_l[j][0], b_l[j][1]);
                    MMA(c[i][j], a_l[i], b_h[j][0], b_h[j][1]);
                }
        }
        __syncthreads();
    }

    // ---- epilogue: alpha*acc + bias, direct fp32 stores
#pragma unroll
    for (int i = 0; i < 4; ++i) {
        int r0 = m0 + wm + i * 16 + (lane >> 2);
#pragma unroll
        for (int j = 0; j < 4; ++j) {
            int cb = wn + j * 8 + (lane & 3) * 2;
            float b0 = bS[cb], b1 = bS[cb + 1];
            float2 v0 = { c[i][j][0] * alpha + b0, c[i][j][1] * alpha + b1 };
            float2 v1 = { c[i][j][2] * alpha + b0, c[i][j][3] * alpha + b1 };
            *(float2*)&C[(size_t)r0 * ldc + n0 + cb] = v0;
            *(float2*)&C[(size_t)(r0 + 8) * ldc + n0 + cb] = v1;
        }
    }
#undef ISSUE
}

// ---------------- ring-softmax: scores(fp32) -> combined weights (bf16 hi/lo) ----------------
__global__ __launch_bounds__(256)
void ring_softmax(const float* __restrict__ scores, bf16* __restrict__ wh, bf16* __restrict__ wl)
{
    const int row = blockIdx.x;
    const size_t off = ((size_t)blockIdx.y * S + row) * S;
    const float* p = scores + off;
    const int tid = threadIdx.x;

    float v[8];
    float mB = -3.0e38f, mC = -3.0e38f;
#pragma unroll
    for (int t = 0; t < 8; ++t) {
        int j = t * 256 + tid;
        v[t] = p[j];
        mB = fmaxf(mB, v[t]);
        if (j <= row) mC = fmaxf(mC, v[t]);
    }

    __shared__ float sm0[8], sm1[8];
    const int wid = tid >> 5, lid = tid & 31;
#pragma unroll
    for (int o = 16; o > 0; o >>= 1) {
        mB = fmaxf(mB, __shfl_xor_sync(0xffffffffu, mB, o));
        mC = fmaxf(mC, __shfl_xor_sync(0xffffffffu, mC, o));
    }
    if (lid == 0) { sm0[wid] = mB; sm1[wid] = mC; }
    __syncthreads();
    mB = sm0[0]; mC = sm1[0];
#pragma unroll
    for (int i = 1; i < 8; ++i) { mB = fmaxf(mB, sm0[i]); mC = fmaxf(mC, sm1[i]); }
    __syncthreads();

    float eb[8];
    float sB = 0.f, sC = 0.f;
#pragma unroll
    for (int t = 0; t < 8; ++t) {
        int j = t * 256 + tid;
        eb[t] = expf(v[t] - mB);
        sB += eb[t];
        if (j <= row) sC += expf(v[t] - mC);
    }
#pragma unroll
    for (int o = 16; o > 0; o >>= 1) {
        sB += __shfl_xor_sync(0xffffffffu, sB, o);
        sC += __shfl_xor_sync(0xffffffffu, sC, o);
    }
    if (lid == 0) { sm0[wid] = sB; sm1[wid] = sC; }
    __syncthreads();
    sB = 0.f; sC = 0.f;
#pragma unroll
    for (int i = 0; i < 8; ++i) { sB += sm0[i]; sC += sm1[i]; }

    const float e     = expf(mC - mB);
    const float cb    = RING_REST / (sB + 1e-8f);
    const float cc    = e / (sC + 1e-8f);
    const float invSe = 1.0f / (e * sC + RING_REST * sB + 1e-8f);
#pragma unroll
    for (int t = 0; t < 8; ++t) {
        int j = t * 256 + tid;
        float w = eb[t] * cb;
        if (j <= row) w += expf(v[t] - mC) * cc;
        w *= invSe;
        bf16 h = __float2bfloat16_rn(w);
        wh[off + j] = h;
        wl[off + j] = __float2bfloat16_rn(w - __bfloat162float(h));
    }
}

// ---------------- launch ----------------
extern "C" void kernel_launch(void* const* d_in, const int* in_sizes, int n_in,
                              void* d_out, int out_size)
{
    (void)in_sizes; (void)n_in; (void)out_size;
    const float* X  = (const float*)d_in[0];
    const float* qw = (const float*)d_in[1];
    const float* qb = (const float*)d_in[2];
    const float* kw = (const float*)d_in[3];
    const float* kb = (const float*)d_in[4];
    const float* vw = (const float*)d_in[5];
    const float* vb = (const float*)d_in[6];
    const float* ow = (const float*)d_in[7];
    const float* ob = (const float*)d_in[8];
    float* out = (float*)d_out;

    bf16 *xh, *xl, *qwh, *qwl, *kwh, *kwl, *vwh, *vwl, *owh, *owl;
    bf16 *qh, *ql, *kh, *kl, *vth, *vtl, *ath, *atl, *wh, *wl;
    float *gq, *gk, *gv, *gattn, *gs;
    cudaGetSymbolAddress((void**)&xh,  g_Xh);  cudaGetSymbolAddress((void**)&xl,  g_Xl);
    cudaGetSymbolAddress((void**)&qwh, g_qwh); cudaGetSymbolAddress((void**)&qwl, g_qwl);
    cudaGetSymbolAddress((void**)&kwh, g_kwh); cudaGetSymbolAddress((void**)&kwl, g_kwl);
    cudaGetSymbolAddress((void**)&vwh, g_vwh); cudaGetSymbolAddress((void**)&vwl, g_vwl);
    cudaGetSymbolAddress((void**)&owh, g_owh); cudaGetSymbolAddress((void**)&owl, g_owl);
    cudaGetSymbolAddress((void**)&gq,  g_q);   cudaGetSymbolAddress((void**)&gk,  g_k);
    cudaGetSymbolAddress((void**)&gv,  g_v);   cudaGetSymbolAddress((void**)&gattn, g_attn);
    cudaGetSymbolAddress((void**)&qh,  g_qh);  cudaGetSymbolAddress((void**)&ql,  g_ql);
    cudaGetSymbolAddress((void**)&kh,  g_kh);  cudaGetSymbolAddress((void**)&kl,  g_kl);
    cudaGetSymbolAddress((void**)&vth, g_vth); cudaGetSymbolAddress((void**)&vtl, g_vtl);
    cudaGetSymbolAddress((void**)&ath, g_ath); cudaGetSymbolAddress((void**)&atl, g_atl);
    cudaGetSymbolAddress((void**)&gs,  g_scores);
    cudaGetSymbolAddress((void**)&wh,  g_wh);  cudaGetSymbolAddress((void**)&wl,  g_wl);

    cudaFuncSetAttribute(gemm_bf3, cudaFuncAttributeMaxDynamicSharedMemorySize, GEMM_SMEM_BYTES);

    const float scale = 0.08838834764831843f;   // 1/sqrt(128)
    const int N4 = S * HID / 4;
    dim3 sblk(256), sgrd(N4 / 256);
    dim3 gblk(256);

    // split inputs + weights to bf16 hi/lo
    split_k<<<sgrd, sblk>>>(X,  xh,  xl,  N4);
    split_k<<<sgrd, sblk>>>(qw, qwh, qwl, N4);
    split_k<<<sgrd, sblk>>>(kw, kwh, kwl, N4);
    split_k<<<sgrd, sblk>>>(vw, vwh, vwl, N4);
    split_k<<<sgrd, sblk>>>(ow, owh, owl, N4);

    // Q/K/V projections (fp32 out)
    gemm_bf3<<<dim3(16, 16, 1), gblk, GEMM_SMEM_BYTES>>>(
        xh, xl, HID, 0, qwh, qwl, HID, 0, qb, gq, HDTOT, 0, HID, 1.0f);
    gemm_bf3<<<dim3(16, 16, 1), gblk, GEMM_SMEM_BYTES>>>(
        xh, xl, HID, 0, kwh, kwl, HID, 0, kb, gk, HDTOT, 0, HID, 1.0f);
    gemm_bf3<<<dim3(16, 16, 1), gblk, GEMM_SMEM_BYTES>>>(
        xh, xl, HID, 0, vwh, vwl, HID, 0, vb, gv, HDTOT, 0, HID, 1.0f);

    // re-split Q/K, transpose-split V
    split_k<<<sgrd, sblk>>>(gq, qh, ql, N4);
    split_k<<<sgrd, sblk>>>(gk, kh, kl, N4);
    transpose_split_k<<<dim3(HDTOT / 32, S / 32), dim3(32, 8)>>>(gv, vth, vtl);

    // scores[h] = scale * Q_h @ K_h^T
    gemm_bf3<<<dim3(16, 16, NHEAD), gblk, GEMM_SMEM_BYTES>>>(
        qh, ql, HDTOT, HDIM, kh, kl, HDTOT, HDIM, nullptr,
        gs, S, (long long)S * S, HDIM, scale);

    // combined ring softmax -> bf16 hi/lo weights
    ring_softmax<<<dim3(S, NHEAD), dim3(256)>>>(gs, wh, wl);

    // attn[h] = W_h @ V_h
    gemm_bf3<<<dim3(1, 16, NHEAD), gblk, GEMM_SMEM_BYTES>>>(
        wh, wl, S, (long long)S * S, vth, vtl, S, (long long)HDIM * S, nullptr,
        gattn, HDTOT, HDIM, S, 1.0f);

    // split attn, output projection
    split_k<<<sgrd, sblk>>>(gattn, ath, atl, N4);
    gemm_bf3<<<dim3(16, 16, 1), gblk, GEMM_SMEM_BYTES>>>(
        ath, atl, HDTOT, 0, owh, owl, HDTOT, 0, ob, out, HID, 0, HDTOT, 1.0f);
}

// round 8
// speedup vs baseline: 2.4796x; 1.1416x over previous
#include <cuda_runtime.h>
#include <cuda_bf16.h>
#include <stdint.h>
#include <math.h>

// Problem constants (fixed by setup_inputs)
#define S     2048
#define HID   2048
#define NHEAD 16
#define HDIM  128
#define HDTOT 2048
#define RING_REST 3.0f   // world_size - 1 identical non-causal ring steps

typedef __nv_bfloat16 bf16;

// ---------------- static device scratch (no runtime allocation allowed) ----------------
__device__ bf16  g_Xh [S * HID],     g_Xl [S * HID];
__device__ bf16  g_qwh[HDTOT * HID], g_qwl[HDTOT * HID];
__device__ bf16  g_kwh[HDTOT * HID], g_kwl[HDTOT * HID];
__device__ bf16  g_vwh[HDTOT * HID], g_vwl[HDTOT * HID];
__device__ bf16  g_owh[HID * HDTOT], g_owl[HID * HDTOT];
__device__ float g_v   [S * HDTOT];
__device__ bf16  g_qh [S * HDTOT], g_ql [S * HDTOT];
__device__ bf16  g_kh [S * HDTOT], g_kl [S * HDTOT];
__device__ bf16  g_vth[HDTOT * S], g_vtl[HDTOT * S];   // V transposed (H*D, S)
__device__ bf16  g_ath[S * HDTOT], g_atl[S * HDTOT];
__device__ float g_scores[(size_t)NHEAD * S * S];      // 256 MB
__device__ bf16  g_wh[(size_t)NHEAD * S * S];          // attention weights hi
__device__ bf16  g_wl[(size_t)NHEAD * S * S];          // attention weights lo

// ---------------- PTX helpers (base compute_103 features only) ----------------
__device__ __forceinline__ uint32_t smem_u32(const void* p) {
    uint32_t a;
    asm("{ .reg .u64 t; cvta.to.shared.u64 t, %1; cvt.u32.u64 %0, t; }" : "=r"(a) : "l"(p));
    return a;
}
__device__ __forceinline__ void cp16(uint32_t s, const void* g) {
    asm volatile("cp.async.cg.shared.global [%0], [%1], 16;" :: "r"(s), "l"(g));
}
#define CP_COMMIT() asm volatile("cp.async.commit_group;" ::: "memory")

#define LDSM4(r, addr) \
    asm volatile("ldmatrix.sync.aligned.m8n8.x4.shared.b16 {%0,%1,%2,%3}, [%4];" \
        : "=r"((r)[0]), "=r"((r)[1]), "=r"((r)[2]), "=r"((r)[3]) : "r"(addr))

#define MMA(cc, aa, b0, b1) \
    asm volatile("mma.sync.aligned.m16n8k16.row.col.f32.bf16.bf16.f32 " \
        "{%0,%1,%2,%3}, {%4,%5,%6,%7}, {%8,%9}, {%0,%1,%2,%3};" \
        : "+f"((cc)[0]), "+f"((cc)[1]), "+f"((cc)[2]), "+f"((cc)[3]) \
        : "r"((aa)[0]), "r"((aa)[1]), "r"((aa)[2]), "r"((aa)[3]), "r"(b0), "r"(b1))

// ---------------- split / transpose conversion kernels ----------------
__global__ __launch_bounds__(256)
void split_k(const float* __restrict__ s, bf16* __restrict__ h, bf16* __restrict__ l, int n4) {
    int i = blockIdx.x * blockDim.x + threadIdx.x;
    if (i >= n4) return;
    float4 v = ((const float4*)s)[i];
    bf16 h0 = __float2bfloat16_rn(v.x), h1 = __float2bfloat16_rn(v.y);
    bf16 h2 = __float2bfloat16_rn(v.z), h3 = __float2bfloat16_rn(v.w);
    bf16 l0 = __float2bfloat16_rn(v.x - __bfloat162float(h0));
    bf16 l1 = __float2bfloat16_rn(v.y - __bfloat162float(h1));
    bf16 l2 = __float2bfloat16_rn(v.z - __bfloat162float(h2));
    bf16 l3 = __float2bfloat16_rn(v.w - __bfloat162float(h3));
    ((__nv_bfloat162*)h)[2 * i]     = __halves2bfloat162(h0, h1);
    ((__nv_bfloat162*)h)[2 * i + 1] = __halves2bfloat162(h2, h3);
    ((__nv_bfloat162*)l)[2 * i]     = __halves2bfloat162(l0, l1);
    ((__nv_bfloat162*)l)[2 * i + 1] = __halves2bfloat162(l2, l3);
}

__global__ __launch_bounds__(256)
void transpose_split_k(const float* __restrict__ src, bf16* __restrict__ th, bf16* __restrict__ tl) {
    __shared__ float tile[32][33];
    int c0 = blockIdx.x * 32, r0 = blockIdx.y * 32;
    int x = threadIdx.x, y = threadIdx.y;   // block (32,8)
#pragma unroll
    for (int i = 0; i < 32; i += 8)
        tile[y + i][x] = src[(size_t)(r0 + y + i) * HDTOT + (c0 + x)];
    __syncthreads();
#pragma unroll
    for (int i = 0; i < 32; i += 8) {
        float v = tile[x][y + i];              // src[r0+x][c0+y+i]
        bf16 h = __float2bfloat16_rn(v);
        size_t o = (size_t)(c0 + y + i) * S + (r0 + x);
        th[o] = h;
        tl[o] = __float2bfloat16_rn(v - __bfloat162float(h));
    }
}

// ---------------- split-bf16 GEMM via mma.sync:  C = alpha*(A*B^T) + bias ----------------
// A (M,K) via Ah/Al, B (N,K) via Bh/Bl, row-major bf16. CTA tile 128x128, BK=32.
// 8 warps as 2(m) x 4(n); warp tile 64x32. 3-stage cp.async pipeline.
// smem per stage: Ah|Al|Bh|Bl each 128x32 bf16 = 8KB -> 32KB; 3 stages = 96KB.
// mode 0: store fp32 C.   mode 1: store bf16 hi/lo split to Ch/Cl.
#define GEMM_SMEM_BYTES 98304

__global__ __launch_bounds__(256)
void gemm_bf3(const bf16* __restrict__ Ah, const bf16* __restrict__ Al, int lda, long long sAz,
              const bf16* __restrict__ Bh, const bf16* __restrict__ Bl, int ldb, long long sBz,
              const float* __restrict__ bias,
              float* __restrict__ C, bf16* __restrict__ Ch, bf16* __restrict__ Cl,
              int ldc, long long sCz,
              int K, float alpha, int mode)
{
    extern __shared__ char smdyn[];
    __shared__ float bS[128];
    const uint32_t smb = smem_u32(smdyn);
    const int tid = threadIdx.x, lane = tid & 31, wid = tid >> 5;
    const int m0 = blockIdx.y * 128, n0 = blockIdx.x * 128;
    const int wm = (wid >> 2) * 64, wn = (wid & 3) * 32;

    Ah += (size_t)blockIdx.z * sAz;  Al += (size_t)blockIdx.z * sAz;
    Bh += (size_t)blockIdx.z * sBz;  Bl += (size_t)blockIdx.z * sBz;
    if (C)  C  += (size_t)blockIdx.z * sCz;
    if (Ch) { Ch += (size_t)blockIdx.z * sCz; Cl += (size_t)blockIdx.z * sCz; }

    if (tid < 128) bS[tid] = bias ? bias[n0 + tid] : 0.f;

    // ---- loader mapping: thread -> (row, chunk pair). 512 chunks (16B) per buffer.
    const int idr = tid >> 1;           // row 0..127
    const int idc = (tid & 1) * 2;      // chunk 0 or 2
    const uint32_t swl = (idr >> 1) & 3;
    const uint32_t s0 = idr * 64 + ((idc ^ swl) << 4);
    const uint32_t s1 = idr * 64 + (((idc + 1) ^ swl) << 4);
    const bf16* gAh = Ah + (size_t)(m0 + idr) * lda + idc * 8;
    const bf16* gAl = Al + (size_t)(m0 + idr) * lda + idc * 8;
    const bf16* gBh = Bh + (size_t)(n0 + idr) * ldb + idc * 8;
    const bf16* gBl = Bl + (size_t)(n0 + idr) * ldb + idc * 8;

#define ISSUE(stg, kt) do {                                                    \
        uint32_t _b = smb + (stg) * 32768;                                     \
        cp16(_b +         s0, gAh + (kt)); cp16(_b +         s1, gAh + (kt) + 8); \
        cp16(_b +  8192 + s0, gAl + (kt)); cp16(_b +  8192 + s1, gAl + (kt) + 8); \
        cp16(_b + 16384 + s0, gBh + (kt)); cp16(_b + 16384 + s1, gBh + (kt) + 8); \
        cp16(_b + 24576 + s0, gBl + (kt)); cp16(_b + 24576 + s1, gBl + (kt) + 8); \
        CP_COMMIT();                                                           \
    } while (0)

    float c[4][4][4];
#pragma unroll
    for (int i = 0; i < 4; ++i)
#pragma unroll
        for (int j = 0; j < 4; ++j)
#pragma unroll
            for (int r = 0; r < 4; ++r) c[i][j][r] = 0.f;

    // lane-fixed pieces of ldmatrix addressing
    const int arow_l = lane & 15;                 // A: row within 16-row tile
    const int achk_l = lane >> 4;                 // A: k-chunk select (0/1)
    const int brow_l = (lane & 7) + ((lane >> 4) << 3);  // B: row within 16-n pair
    const int bchk_l = (lane >> 3) & 1;           // B: k-chunk select (0/1)

    const int nk = K / 32;                        // always >= 4 here
    ISSUE(0, 0);
    ISSUE(1, 32);

    for (int kt = 0; kt < nk; ++kt) {
        if (kt + 2 < nk) {
            ISSUE((kt + 2) % 3, (kt + 2) * 32);
            asm volatile("cp.async.wait_group 2;" ::: "memory");
        } else if (kt + 1 < nk) {
            asm volatile("cp.async.wait_group 1;" ::: "memory");
        } else {
            asm volatile("cp.async.wait_group 0;" ::: "memory");
        }
        __syncthreads();

        const uint32_t base = smb + (kt % 3) * 32768;
#pragma unroll
        for (int kk = 0; kk < 2; ++kk) {          // two k16 halves of BK=32
            const int c0 = kk * 2;
            uint32_t a_h[4][4], a_l[4][4];
            const int ac = c0 + achk_l;
#pragma unroll
            for (int i = 0; i < 4; ++i) {
                int row = wm + i * 16 + arow_l;
                uint32_t ph = row * 64 + ((ac ^ ((row >> 1) & 3)) << 4);
                LDSM4(a_h[i], base + ph);
                LDSM4(a_l[i], base + 8192 + ph);
            }
            uint32_t b_h[4][2], b_l[4][2];
            const int bc = c0 + bchk_l;
#pragma unroll
            for (int j2 = 0; j2 < 2; ++j2) {
                int row = wn + j2 * 16 + brow_l;
                uint32_t ph = row * 64 + ((bc ^ ((row >> 1) & 3)) << 4);
                uint32_t r[4];
                LDSM4(r, base + 16384 + ph);
                b_h[2 * j2][0] = r[0]; b_h[2 * j2][1] = r[1];
                b_h[2 * j2 + 1][0] = r[2]; b_h[2 * j2 + 1][1] = r[3];
                LDSM4(r, base + 24576 + ph);
                b_l[2 * j2][0] = r[0]; b_l[2 * j2][1] = r[1];
                b_l[2 * j2 + 1][0] = r[2]; b_l[2 * j2 + 1][1] = r[3];
            }
#pragma unroll
            for (int i = 0; i < 4; ++i)
#pragma unroll
                for (int j = 0; j < 4; ++j) {
                    MMA(c[i][j], a_h[i], b_h[j][0], b_h[j][1]);
                    MMA(c[i][j], a_h[i], b_l[j][0], b_l[j][1]);
                    MMA(c[i][j], a_l[i], b_h[j][0], b_h[j][1]);
                }
        }
        __syncthreads();
    }

    // ---- epilogue
#pragma unroll
    for (int i = 0; i < 4; ++i) {
        int r0 = m0 + wm + i * 16 + (lane >> 2);
#pragma unroll
        for (int j = 0; j < 4; ++j) {
            int cb = wn + j * 8 + (lane & 3) * 2;
            float b0 = bS[cb], b1 = bS[cb + 1];
            float x0 = c[i][j][0] * alpha + b0, x1 = c[i][j][1] * alpha + b1;
            float x2 = c[i][j][2] * alpha + b0, x3 = c[i][j][3] * alpha + b1;
            if (mode == 0) {
                float2 v0 = { x0, x1 }, v1 = { x2, x3 };
                *(float2*)&C[(size_t)r0 * ldc + n0 + cb] = v0;
                *(float2*)&C[(size_t)(r0 + 8) * ldc + n0 + cb] = v1;
            } else {
                bf16 h0 = __float2bfloat16_rn(x0), h1 = __float2bfloat16_rn(x1);
                bf16 h2 = __float2bfloat16_rn(x2), h3 = __float2bfloat16_rn(x3);
                *(__nv_bfloat162*)&Ch[(size_t)r0 * ldc + n0 + cb] = __halves2bfloat162(h0, h1);
                *(__nv_bfloat162*)&Cl[(size_t)r0 * ldc + n0 + cb] = __halves2bfloat162(
                    __float2bfloat16_rn(x0 - __bfloat162float(h0)),
                    __float2bfloat16_rn(x1 - __bfloat162float(h1)));
                *(__nv_bfloat162*)&Ch[(size_t)(r0 + 8) * ldc + n0 + cb] = __halves2bfloat162(h2, h3);
                *(__nv_bfloat162*)&Cl[(size_t)(r0 + 8) * ldc + n0 + cb] = __halves2bfloat162(
                    __float2bfloat16_rn(x2 - __bfloat162float(h2)),
                    __float2bfloat16_rn(x3 - __bfloat162float(h3)));
            }
        }
    }
#undef ISSUE
}

// ---------------- ring-softmax: scores(fp32) -> combined weights (bf16 hi/lo) ----------------
__global__ __launch_bounds__(256)
void ring_softmax(const float* __restrict__ scores, bf16* __restrict__ wh, bf16* __restrict__ wl)
{
    const int row = blockIdx.x;
    const size_t off = ((size_t)blockIdx.y * S + row) * S;
    const float* p = scores + off;
    const int tid = threadIdx.x;

    float v[8];
    float mB = -3.0e38f, mC = -3.0e38f;
#pragma unroll
    for (int t = 0; t < 8; ++t) {
        int j = t * 256 + tid;
        v[t] = p[j];
        mB = fmaxf(mB, v[t]);
        if (j <= row) mC = fmaxf(mC, v[t]);
    }

    __shared__ float sm0[8], sm1[8];
    const int wid = tid >> 5, lid = tid & 31;
#pragma unroll
    for (int o = 16; o > 0; o >>= 1) {
        mB = fmaxf(mB, __shfl_xor_sync(0xffffffffu, mB, o));
        mC = fmaxf(mC, __shfl_xor_sync(0xffffffffu, mC, o));
    }
    if (lid == 0) { sm0[wid] = mB; sm1[wid] = mC; }
    __syncthreads();
    mB = sm0[0]; mC = sm1[0];
#pragma unroll
    for (int i = 1; i < 8; ++i) { mB = fmaxf(mB, sm0[i]); mC = fmaxf(mC, sm1[i]); }
    __syncthreads();

    float eb[8];
    float sB = 0.f, sC = 0.f;
#pragma unroll
    for (int t = 0; t < 8; ++t) {
        int j = t * 256 + tid;
        eb[t] = expf(v[t] - mB);
        sB += eb[t];
        if (j <= row) sC += expf(v[t] - mC);
    }
#pragma unroll
    for (int o = 16; o > 0; o >>= 1) {
        sB += __shfl_xor_sync(0xffffffffu, sB, o);
        sC += __shfl_xor_sync(0xffffffffu, sC, o);
    }
    if (lid == 0) { sm0[wid] = sB; sm1[wid] = sC; }
    __syncthreads();
    sB = 0.f; sC = 0.f;
#pragma unroll
    for (int i = 0; i < 8; ++i) { sB += sm0[i]; sC += sm1[i]; }

    const float e     = expf(mC - mB);
    const float cb    = RING_REST / (sB + 1e-8f);
    const float cc    = e / (sC + 1e-8f);
    const float invSe = 1.0f / (e * sC + RING_REST * sB + 1e-8f);
#pragma unroll
    for (int t = 0; t < 8; ++t) {
        int j = t * 256 + tid;
        float w = eb[t] * cb;
        if (j <= row) w += expf(v[t] - mC) * cc;
        w *= invSe;
        bf16 h = __float2bfloat16_rn(w);
        wh[off + j] = h;
        wl[off + j] = __float2bfloat16_rn(w - __bfloat162float(h));
    }
}

// ---------------- launch ----------------
extern "C" void kernel_launch(void* const* d_in, const int* in_sizes, int n_in,
                              void* d_out, int out_size)
{
    (void)in_sizes; (void)n_in; (void)out_size;
    const float* X  = (const float*)d_in[0];
    const float* qw = (const float*)d_in[1];
    const float* qb = (const float*)d_in[2];
    const float* kw = (const float*)d_in[3];
    const float* kb = (const float*)d_in[4];
    const float* vw = (const float*)d_in[5];
    const float* vb = (const float*)d_in[6];
    const float* ow = (const float*)d_in[7];
    const float* ob = (const float*)d_in[8];
    float* out = (float*)d_out;

    bf16 *xh, *xl, *qwh, *qwl, *kwh, *kwl, *vwh, *vwl, *owh, *owl;
    bf16 *qh, *ql, *kh, *kl, *vth, *vtl, *ath, *atl, *wh, *wl;
    float *gv, *gs;
    cudaGetSymbolAddress((void**)&xh,  g_Xh);  cudaGetSymbolAddress((void**)&xl,  g_Xl);
    cudaGetSymbolAddress((void**)&qwh, g_qwh); cudaGetSymbolAddress((void**)&qwl, g_qwl);
    cudaGetSymbolAddress((void**)&kwh, g_kwh); cudaGetSymbolAddress((void**)&kwl, g_kwl);
    cudaGetSymbolAddress((void**)&vwh, g_vwh); cudaGetSymbolAddress((void**)&vwl, g_vwl);
    cudaGetSymbolAddress((void**)&owh, g_owh); cudaGetSymbolAddress((void**)&owl, g_owl);
    cudaGetSymbolAddress((void**)&gv,  g_v);
    cudaGetSymbolAddress((void**)&qh,  g_qh);  cudaGetSymbolAddress((void**)&ql,  g_ql);
    cudaGetSymbolAddress((void**)&kh,  g_kh);  cudaGetSymbolAddress((void**)&kl,  g_kl);
    cudaGetSymbolAddress((void**)&vth, g_vth); cudaGetSymbolAddress((void**)&vtl, g_vtl);
    cudaGetSymbolAddress((void**)&ath, g_ath); cudaGetSymbolAddress((void**)&atl, g_atl);
    cudaGetSymbolAddress((void**)&gs,  g_scores);
    cudaGetSymbolAddress((void**)&wh,  g_wh);  cudaGetSymbolAddress((void**)&wl,  g_wl);

    cudaFuncSetAttribute(gemm_bf3, cudaFuncAttributeMaxDynamicSharedMemorySize, GEMM_SMEM_BYTES);

    const float scale = 0.08838834764831843f;   // 1/sqrt(128)
    const int N4 = S * HID / 4;
    dim3 sblk(256), sgrd(N4 / 256);
    dim3 gblk(256);

    // split inputs + weights to bf16 hi/lo
    split_k<<<sgrd, sblk>>>(X,  xh,  xl,  N4);
    split_k<<<sgrd, sblk>>>(qw, qwh, qwl, N4);
    split_k<<<sgrd, sblk>>>(kw, kwh, kwl, N4);
    split_k<<<sgrd, sblk>>>(vw, vwh, vwl, N4);
    split_k<<<sgrd, sblk>>>(ow, owh, owl, N4);

    // Q/K projections -> split bf16 directly (fused epilogue); V -> fp32 for transpose
    gemm_bf3<<<dim3(16, 16, 1), gblk, GEMM_SMEM_BYTES>>>(
        xh, xl, HID, 0, qwh, qwl, HID, 0, qb,
        nullptr, qh, ql, HDTOT, 0, HID, 1.0f, 1);
    gemm_bf3<<<dim3(16, 16, 1), gblk, GEMM_SMEM_BYTES>>>(
        xh, xl, HID, 0, kwh, kwl, HID, 0, kb,
        nullptr, kh, kl, HDTOT, 0, HID, 1.0f, 1);
    gemm_bf3<<<dim3(16, 16, 1), gblk, GEMM_SMEM_BYTES>>>(
        xh, xl, HID, 0, vwh, vwl, HID, 0, vb,
        gv, nullptr, nullptr, HDTOT, 0, HID, 1.0f, 0);

    // transpose-split V
    transpose_split_k<<<dim3(HDTOT / 32, S / 32), dim3(32, 8)>>>(gv, vth, vtl);

    // scores[h] = scale * Q_h @ K_h^T  (fp32 out for softmax precision)
    gemm_bf3<<<dim3(16, 16, NHEAD), gblk, GEMM_SMEM_BYTES>>>(
        qh, ql, HDTOT, HDIM, kh, kl, HDTOT, HDIM, nullptr,
        gs, nullptr, nullptr, S, (long long)S * S, HDIM, scale, 0);

    // combined ring softmax -> bf16 hi/lo weights
    ring_softmax<<<dim3(S, NHEAD), dim3(256)>>>(gs, wh, wl);

    // attn[h] = W_h @ V_h -> split bf16 directly
    gemm_bf3<<<dim3(1, 16, NHEAD), gblk, GEMM_SMEM_BYTES>>>(
        wh, wl, S, (long long)S * S, vth, vtl, S, (long long)HDIM * S, nullptr,
        nullptr, ath, atl, HDTOT, HDIM, S, 1.0f, 1);

    // output projection (fp32 to d_out)
    gemm_bf3<<<dim3(16, 16, 1), gblk, GEMM_SMEM_BYTES>>>(
        ath, atl, HDTOT, 0, owh, owl, HDTOT, 0, ob,
        out, nullptr, nullptr, HID, 0, HDTOT, 1.0f, 0);
}